// round 2
// baseline (speedup 1.0000x reference)
#include <cuda_runtime.h>
#include <math.h>

#define NN 100000
#define EMAX 2000000

// Scratch (device globals — no allocation allowed)
__device__ int   g_is32;
__device__ int   g_src[EMAX / 2];
__device__ int   g_dst[EMAX / 2];
__device__ float g_deg[NN];
__device__ float g_dinv[NN];
__device__ float g_norm[EMAX / 2];
__device__ float g_bufA[(size_t)NN * 100];
__device__ float g_bufB[(size_t)NN * 100];

// ---------------- edge dtype detection + normalization ----------------
// If the buffer is int32, reinterpreting pairs as int64 gives lo + hi*2^32 with
// hi ~ U[0,100000) -> out of [0,NN) almost surely within the first few entries.
__global__ void k_detect(const long long* __restrict__ edge64, int E) {
    if (threadIdx.x == 0) g_is32 = 0;
    __syncthreads();
    int nscan = E < 4096 ? E : 4096;
    for (int i = threadIdx.x; i < nscan; i += blockDim.x) {
        long long v = edge64[i];
        if (v < 0 || v >= NN) g_is32 = 1;  // benign race: all write 1
    }
}

__global__ void k_convert(const void* __restrict__ edge, int E) {
    int e = blockIdx.x * blockDim.x + threadIdx.x;
    if (e >= E) return;
    if (g_is32) {
        const int* p = (const int*)edge;
        g_src[e] = p[e];
        g_dst[e] = p[E + e];
    } else {
        const long long* p = (const long long*)edge;
        g_src[e] = (int)p[e];
        g_dst[e] = (int)p[E + e];
    }
}

// ---------------- degree / norm precompute ----------------
__global__ void k_zero_deg() {
    int i = blockIdx.x * blockDim.x + threadIdx.x;
    if (i < NN) g_deg[i] = 0.0f;
}

__global__ void k_count_deg(int E) {
    int e = blockIdx.x * blockDim.x + threadIdx.x;
    if (e < E) atomicAdd(&g_deg[g_dst[e]], 1.0f);
}

__global__ void k_dinv() {
    int i = blockIdx.x * blockDim.x + threadIdx.x;
    if (i < NN) g_dinv[i] = rsqrtf(g_deg[i] + 1.0f);  // +1 = self loop
}

__global__ void k_norm(int E) {
    int e = blockIdx.x * blockDim.x + threadIdx.x;
    if (e < E) g_norm[e] = g_dinv[g_src[e]] * g_dinv[g_dst[e]];
}

// ---------------- self-loop init: out[i,f] = x[i,f] * dinv[i]^2 ----------------
template <int F>
__global__ void k_init_self(const float* __restrict__ x, float* __restrict__ out) {
    unsigned idx = blockIdx.x * blockDim.x + threadIdx.x;
    if (idx >= (unsigned)NN * F) return;
    int i = idx / F;
    float d = g_dinv[i];
    out[idx] = x[idx] * d * d;
}

// ---------------- edge scatter: out[dst] += x[src] * norm[e] ----------------
template <int F>
__global__ void k_scatter(const float* __restrict__ x, float* __restrict__ out, int E) {
    unsigned idx = blockIdx.x * blockDim.x + threadIdx.x;
    unsigned total = (unsigned)E * F;
    if (idx >= total) return;
    int e = idx / F;
    int f = idx - e * F;
    int s = g_src[e];
    int d = g_dst[e];
    atomicAdd(&out[(size_t)d * F + f], x[(size_t)s * F + f] * g_norm[e]);
}

// ---------------- small dense GEMM: Y = X @ W (+ bias, relu) ----------------
// X: [n, IN] row-major, W: [IN, OUT] row-major, Y: [n, OUT]
template <int IN, int OUT, bool EPI>
__global__ void k_gemm(const float* __restrict__ X, const float* __restrict__ W,
                       const float* __restrict__ bias, float* __restrict__ Y, int n) {
    __shared__ float Xs[64 * IN];
    __shared__ float Ws[IN * OUT];
    int base = blockIdx.x * 64;
    for (int i = threadIdx.x; i < IN * OUT; i += blockDim.x) Ws[i] = W[i];
    int rows = n - base;
    if (rows > 64) rows = 64;
    for (int i = threadIdx.x; i < rows * IN; i += blockDim.x)
        Xs[i] = X[(size_t)base * IN + i];
    __syncthreads();
    for (int idx = threadIdx.x; idx < rows * OUT; idx += blockDim.x) {
        int r = idx / OUT;
        int c = idx - r * OUT;
        float acc = EPI ? bias[c] : 0.0f;
        const float* xr = &Xs[r * IN];
#pragma unroll 8
        for (int k = 0; k < IN; k++) acc = fmaf(xr[k], Ws[k * OUT + c], acc);
        if (EPI) acc = fmaxf(acc, 0.0f);
        Y[((size_t)base + r) * OUT + c] = acc;
    }
}

// ---------------- bias + relu in place ----------------
template <int F>
__global__ void k_bias_relu(float* __restrict__ x, const float* __restrict__ b) {
    unsigned idx = blockIdx.x * blockDim.x + threadIdx.x;
    if (idx >= (unsigned)NN * F) return;
    int f = idx % F;
    x[idx] = fmaxf(x[idx] + b[f], 0.0f);
}

// ---------------- fused epilogue: relu(agg3+b3) -> MLP 25->25->10->1 ----------------
__global__ void k_final(const float* __restrict__ agg, const float* __restrict__ b3,
                        const float* __restrict__ Wl1, const float* __restrict__ bl1,
                        const float* __restrict__ Wl2, const float* __restrict__ bl2,
                        const float* __restrict__ Wl3, const float* __restrict__ bl3,
                        float* __restrict__ out, int n) {
    __shared__ float sW1[25 * 25], sW2[25 * 10], sW3[10];
    __shared__ float sb3[25], sb1[25], sb2[10], sb3l;
    for (int i = threadIdx.x; i < 25 * 25; i += blockDim.x) sW1[i] = Wl1[i];
    for (int i = threadIdx.x; i < 25 * 10; i += blockDim.x) sW2[i] = Wl2[i];
    if (threadIdx.x < 10) sW3[threadIdx.x] = Wl3[threadIdx.x];
    if (threadIdx.x < 25) { sb3[threadIdx.x] = b3[threadIdx.x]; sb1[threadIdx.x] = bl1[threadIdx.x]; }
    if (threadIdx.x < 10) sb2[threadIdx.x] = bl2[threadIdx.x];
    if (threadIdx.x == 0) sb3l = bl3[0];
    __syncthreads();

    int i = blockIdx.x * blockDim.x + threadIdx.x;
    if (i >= n) return;

    float v[25];
#pragma unroll
    for (int f = 0; f < 25; f++)
        v[f] = fmaxf(agg[(size_t)i * 25 + f] + sb3[f], 0.0f);

    float h1[25];
#pragma unroll
    for (int c = 0; c < 25; c++) {
        float a = sb1[c];
#pragma unroll
        for (int k = 0; k < 25; k++) a = fmaf(v[k], sW1[k * 25 + c], a);
        h1[c] = fmaxf(a, 0.0f);
    }
    float h2[10];
#pragma unroll
    for (int c = 0; c < 10; c++) {
        float a = sb2[c];
#pragma unroll
        for (int k = 0; k < 25; k++) a = fmaf(h1[k], sW2[k * 10 + c], a);
        h2[c] = fmaxf(a, 0.0f);
    }
    float o = sb3l;
#pragma unroll
    for (int k = 0; k < 10; k++) o = fmaf(h2[k], sW3[k], o);
    out[i] = fmaxf(o, 0.0f);
}

// ---------------- launch ----------------
extern "C" void kernel_launch(void* const* d_in, const int* in_sizes, int n_in,
                              void* d_out, int out_size) {
    const float* x   = (const float*)d_in[0];
    const float* W1  = (const float*)d_in[1];
    const float* b1  = (const float*)d_in[2];
    const float* W2  = (const float*)d_in[3];
    const float* b2  = (const float*)d_in[4];
    const float* W3  = (const float*)d_in[5];
    const float* b3  = (const float*)d_in[6];
    const float* Wl1 = (const float*)d_in[7];
    const float* bl1 = (const float*)d_in[8];
    const float* Wl2 = (const float*)d_in[9];
    const float* bl2 = (const float*)d_in[10];
    const float* Wl3 = (const float*)d_in[11];
    const float* bl3 = (const float*)d_in[12];
    const void* edge = d_in[13];
    int E = in_sizes[13] / 2;

    float *A, *B;
    cudaGetSymbolAddress((void**)&A, g_bufA);
    cudaGetSymbolAddress((void**)&B, g_bufB);

    const int T = 256;
    int gN = (NN + T - 1) / T;
    int gE = (E + T - 1) / T;

    // normalize edge indices (int32 vs int64) into g_src/g_dst
    k_detect<<<1, 256>>>((const long long*)edge, E);
    k_convert<<<gE, T>>>(edge, E);

    // precompute dinv / per-edge norm (shared across the 3 GCN layers)
    k_zero_deg<<<gN, T>>>();
    k_count_deg<<<gE, T>>>(E);
    k_dinv<<<gN, T>>>();
    k_norm<<<gE, T>>>(E);

    int gemmG = (NN + 63) / 64;

    // ----- Layer 1: aggregate in 64-dim (input side), then GEMM 64->100 -----
    k_init_self<64><<<((unsigned)NN * 64 + T - 1) / T, T>>>(x, A);
    k_scatter<64><<<((unsigned)E * 64 + T - 1) / T, T>>>(x, A, E);
    k_gemm<64, 100, true><<<gemmG, T>>>(A, W1, b1, B, NN);          // B = h1

    // ----- Layer 2: GEMM 100->50 first, aggregate in 50-dim -----
    k_gemm<100, 50, false><<<gemmG, T>>>(B, W2, nullptr, A, NN);    // A = t2
    k_init_self<50><<<((unsigned)NN * 50 + T - 1) / T, T>>>(A, B);
    k_scatter<50><<<((unsigned)E * 50 + T - 1) / T, T>>>(A, B, E);
    k_bias_relu<50><<<((unsigned)NN * 50 + T - 1) / T, T>>>(B, b2); // B = h2

    // ----- Layer 3: GEMM 50->25 first, aggregate in 25-dim -----
    k_gemm<50, 25, false><<<gemmG, T>>>(B, W3, nullptr, A, NN);     // A = t3
    k_init_self<25><<<((unsigned)NN * 25 + T - 1) / T, T>>>(A, B);
    k_scatter<25><<<((unsigned)E * 25 + T - 1) / T, T>>>(A, B, E);

    // ----- fused: relu(agg3+b3) -> MLP 25->25->10->1 -----
    k_final<<<gN, T>>>(B, b3, Wl1, bl1, Wl2, bl2, Wl3, bl3, (float*)d_out, NN);
}

// round 3
// speedup vs baseline: 1.5054x; 1.5054x over previous
#include <cuda_runtime.h>
#include <math.h>

#define NN 100000
#define EMAXE 1000000

// Scratch (device globals — no allocation allowed)
__device__ int   g_is32;
__device__ int   g_src[EMAXE];
__device__ int   g_dst[EMAXE];
__device__ float g_deg[NN];
__device__ float g_dinv[NN];
__device__ float g_norm[EMAXE];
__device__ __align__(16) float g_bufA[(size_t)NN * 100];  // 40MB
__device__ __align__(16) float g_bufB[(size_t)NN * 100];  // 40MB
__device__ __align__(16) float g_bufC[(size_t)NN * 52];   // 20.8MB

// ---------------- vector reduction helper ----------------
__device__ __forceinline__ void red_add_v4(float* addr, float4 v) {
    asm volatile("red.global.add.v4.f32 [%0], {%1,%2,%3,%4};"
                 :: "l"(addr), "f"(v.x), "f"(v.y), "f"(v.z), "f"(v.w)
                 : "memory");
}

// ---------------- edge dtype detection + normalization ----------------
__global__ void k_detect(const long long* __restrict__ edge64, int E) {
    if (threadIdx.x == 0) g_is32 = 0;
    __syncthreads();
    int nscan = E < 4096 ? E : 4096;
    for (int i = threadIdx.x; i < nscan; i += blockDim.x) {
        long long v = edge64[i];
        if (v < 0 || v >= NN) g_is32 = 1;  // benign race
    }
}

__global__ void k_convert(const void* __restrict__ edge, int E) {
    int e = blockIdx.x * blockDim.x + threadIdx.x;
    if (e >= E) return;
    if (g_is32) {
        const int* p = (const int*)edge;
        g_src[e] = p[e];
        g_dst[e] = p[E + e];
    } else {
        const long long* p = (const long long*)edge;
        g_src[e] = (int)p[e];
        g_dst[e] = (int)p[E + e];
    }
}

// ---------------- degree / norm precompute ----------------
__global__ void k_zero_deg() {
    int i = blockIdx.x * blockDim.x + threadIdx.x;
    if (i < NN) g_deg[i] = 0.0f;
}

__global__ void k_count_deg(int E) {
    int e = blockIdx.x * blockDim.x + threadIdx.x;
    if (e < E) atomicAdd(&g_deg[g_dst[e]], 1.0f);
}

__global__ void k_dinv() {
    int i = blockIdx.x * blockDim.x + threadIdx.x;
    if (i < NN) g_dinv[i] = rsqrtf(g_deg[i] + 1.0f);  // +1 = self loop
}

__global__ void k_norm(int E) {
    int e = blockIdx.x * blockDim.x + threadIdx.x;
    if (e < E) g_norm[e] = g_dinv[g_src[e]] * g_dinv[g_dst[e]];
}

// ---------------- self-loop init (layer 1): out = x * dinv^2, v4 ----------------
__global__ void k_init64(const float* __restrict__ x, float* __restrict__ out) {
    int idx = blockIdx.x * blockDim.x + threadIdx.x;  // NN*16 chunks
    if (idx >= NN * 16) return;
    int i = idx >> 4;
    float d = g_dinv[i];
    float s = d * d;
    float4 v = *(const float4*)(x + (size_t)idx * 4);
    v.x *= s; v.y *= s; v.z *= s; v.w *= s;
    *(float4*)(out + (size_t)idx * 4) = v;
}

// ---------------- edge scatter: out[dst] += x[src]*norm, v4 chunks ----------------
template <int LD>
__global__ void k_scatter4(const float* __restrict__ x, float* __restrict__ out, int E) {
    constexpr int C = LD / 4;
    int idx = blockIdx.x * blockDim.x + threadIdx.x;
    if (idx >= E * C) return;
    int e = idx / C;
    int c = idx - e * C;
    int s = g_src[e];
    int d = g_dst[e];
    float nrm = g_norm[e];
    float4 v = *(const float4*)(x + (size_t)s * LD + c * 4);
    v.x *= nrm; v.y *= nrm; v.z *= nrm; v.w *= nrm;
    red_add_v4(out + (size_t)d * LD + c * 4, v);
}

// ---------------- small dense GEMM with fused prologue/epilogues ----------------
// X: [n, LDX] (IN valid cols), W: [IN, OUT], Y/Yacc: [n, LDY] (OUT valid, rest 0)
// IN_BR:  apply relu(x + bin) to loaded X columns
// O_BR:   Y = relu(y + bout)
// O_SELF: write Y = y (raw) and Yacc = y * dinv[row]^2
template <int IN, int LDX, int OUT, int LDY, bool IN_BR, bool O_BR, bool O_SELF>
__global__ void k_gemm(const float* __restrict__ X, const float* __restrict__ W,
                       const float* __restrict__ bin, const float* __restrict__ bout,
                       float* __restrict__ Y, float* __restrict__ Yacc, int n) {
    __shared__ float Xs[64 * IN];
    __shared__ float Ws[IN * OUT];
    __shared__ float bs[IN_BR ? IN : 1];
    int base = blockIdx.x * 64;
    for (int i = threadIdx.x; i < IN * OUT; i += blockDim.x) Ws[i] = W[i];
    if (IN_BR)
        for (int i = threadIdx.x; i < IN; i += blockDim.x) bs[i] = bin[i];
    __syncthreads();  // bs ready before use below
    int rows = n - base;
    if (rows > 64) rows = 64;
    for (int i = threadIdx.x; i < rows * IN; i += blockDim.x) {
        int r = i / IN, c = i - r * IN;
        float v = X[((size_t)base + r) * LDX + c];
        if (IN_BR) v = fmaxf(v + bs[c], 0.0f);
        Xs[i] = v;
    }
    __syncthreads();
    for (int idx = threadIdx.x; idx < rows * LDY; idx += blockDim.x) {
        int r = idx / LDY;
        int c = idx - r * LDY;
        float acc = 0.0f;
        if (c < OUT) {
            acc = O_BR ? bout[c] : 0.0f;
            const float* xr = &Xs[r * IN];
#pragma unroll 8
            for (int k = 0; k < IN; k++) acc = fmaf(xr[k], Ws[k * OUT + c], acc);
            if (O_BR) acc = fmaxf(acc, 0.0f);
        }
        size_t o = ((size_t)base + r) * LDY + c;
        Y[o] = acc;
        if (O_SELF) {
            float d = g_dinv[base + r];
            Yacc[o] = acc * d * d;
        }
    }
}

// ---------------- fused epilogue: relu(agg3+b3) -> MLP 25->25->10->1 ----------------
__global__ void k_final(const float* __restrict__ agg, const float* __restrict__ b3,
                        const float* __restrict__ Wl1, const float* __restrict__ bl1,
                        const float* __restrict__ Wl2, const float* __restrict__ bl2,
                        const float* __restrict__ Wl3, const float* __restrict__ bl3,
                        float* __restrict__ out, int n) {
    __shared__ float sW1[25 * 25], sW2[25 * 10], sW3[10];
    __shared__ float sb3[25], sb1[25], sb2[10], sb3l;
    for (int i = threadIdx.x; i < 25 * 25; i += blockDim.x) sW1[i] = Wl1[i];
    for (int i = threadIdx.x; i < 25 * 10; i += blockDim.x) sW2[i] = Wl2[i];
    if (threadIdx.x < 10) sW3[threadIdx.x] = Wl3[threadIdx.x];
    if (threadIdx.x < 25) { sb3[threadIdx.x] = b3[threadIdx.x]; sb1[threadIdx.x] = bl1[threadIdx.x]; }
    if (threadIdx.x < 10) sb2[threadIdx.x] = bl2[threadIdx.x];
    if (threadIdx.x == 0) sb3l = bl3[0];
    __syncthreads();

    int i = blockIdx.x * blockDim.x + threadIdx.x;
    if (i >= n) return;

    float v[25];
#pragma unroll
    for (int f = 0; f < 25; f++)
        v[f] = fmaxf(agg[(size_t)i * 28 + f] + sb3[f], 0.0f);

    float h1[25];
#pragma unroll
    for (int c = 0; c < 25; c++) {
        float a = sb1[c];
#pragma unroll
        for (int k = 0; k < 25; k++) a = fmaf(v[k], sW1[k * 25 + c], a);
        h1[c] = fmaxf(a, 0.0f);
    }
    float h2[10];
#pragma unroll
    for (int c = 0; c < 10; c++) {
        float a = sb2[c];
#pragma unroll
        for (int k = 0; k < 25; k++) a = fmaf(h1[k], sW2[k * 10 + c], a);
        h2[c] = fmaxf(a, 0.0f);
    }
    float o = sb3l;
#pragma unroll
    for (int k = 0; k < 10; k++) o = fmaf(h2[k], sW3[k], o);
    out[i] = fmaxf(o, 0.0f);
}

// ---------------- launch ----------------
extern "C" void kernel_launch(void* const* d_in, const int* in_sizes, int n_in,
                              void* d_out, int out_size) {
    const float* x   = (const float*)d_in[0];
    const float* W1  = (const float*)d_in[1];
    const float* b1  = (const float*)d_in[2];
    const float* W2  = (const float*)d_in[3];
    const float* b2  = (const float*)d_in[4];
    const float* W3  = (const float*)d_in[5];
    const float* b3  = (const float*)d_in[6];
    const float* Wl1 = (const float*)d_in[7];
    const float* bl1 = (const float*)d_in[8];
    const float* Wl2 = (const float*)d_in[9];
    const float* bl2 = (const float*)d_in[10];
    const float* Wl3 = (const float*)d_in[11];
    const float* bl3 = (const float*)d_in[12];
    const void* edge = d_in[13];
    int E = in_sizes[13] / 2;

    float *A, *B, *C;
    cudaGetSymbolAddress((void**)&A, g_bufA);
    cudaGetSymbolAddress((void**)&B, g_bufB);
    cudaGetSymbolAddress((void**)&C, g_bufC);

    const int T = 256;
    int gN = (NN + T - 1) / T;
    int gE = (E + T - 1) / T;

    // normalize edge indices (int32 vs int64) into g_src/g_dst
    k_detect<<<1, 256>>>((const long long*)edge, E);
    k_convert<<<gE, T>>>(edge, E);

    // dinv / per-edge norm (shared across the 3 GCN layers)
    k_zero_deg<<<gN, T>>>();
    k_count_deg<<<gE, T>>>(E);
    k_dinv<<<gN, T>>>();
    k_norm<<<gE, T>>>(E);

    int gemmG = (NN + 63) / 64;

    // ----- Layer 1: aggregate input (64-dim), then GEMM 64->100 (+b1, relu) -----
    k_init64<<<(NN * 16 + T - 1) / T, T>>>(x, A);
    k_scatter4<64><<<(E * 16 + T - 1) / T, T>>>(x, A, E);
    k_gemm<64, 64, 100, 100, false, true, false><<<gemmG, T>>>(
        A, W1, nullptr, b1, B, nullptr, NN);                       // B = h1

    // ----- Layer 2: GEMM 100->50 (raw->A ld52, self-acc->C), aggregate -----
    k_gemm<100, 100, 50, 52, false, false, true><<<gemmG, T>>>(
        B, W2, nullptr, nullptr, A, C, NN);                        // A=t2 raw, C=acc
    k_scatter4<52><<<(E * 13 + T - 1) / T, T>>>(A, C, E);          // C = agg2 (pre bias/relu)

    // ----- Layer 3: GEMM 50->25 with fused relu(in+b2); raw->A ld28, acc->B -----
    k_gemm<50, 52, 25, 28, true, false, true><<<gemmG, T>>>(
        C, W3, b2, nullptr, A, B, NN);                             // A=t3 raw, B=acc
    k_scatter4<28><<<(E * 7 + T - 1) / T, T>>>(A, B, E);           // B = agg3 (pre bias/relu)

    // ----- fused: relu(agg3+b3) -> MLP 25->25->10->1 -----
    k_final<<<gN, T>>>(B, b3, Wl1, bl1, Wl2, bl2, Wl3, bl3, (float*)d_out, NN);
}

// round 4
// speedup vs baseline: 2.7430x; 1.8220x over previous
#include <cuda_runtime.h>
#include <math.h>

#define NN 100000
#define EE 1000000
#define SCH 512                     // scan chunk
#define NBLK ((NN + SCH - 1) / SCH) // 196

// Scratch (device globals — no allocation allowed)
__device__ int   g_is32;
__device__ int   g_src[EE];
__device__ int   g_dst[EE];
__device__ int   g_csr[EE];
__device__ int   g_degi[NN];
__device__ int   g_off[NN + 1];
__device__ int   g_cur[NN];
__device__ int   g_part[NBLK];
__device__ int   g_carry[NBLK];
__device__ float g_dinv[NN];
__device__ float g_b2p[52];
__device__ __align__(16) float g_bufA[(size_t)NN * 100];
__device__ __align__(16) float g_bufB[(size_t)NN * 100];
__device__ __align__(16) float g_bufC[(size_t)NN * 52];

// ---------------- edge dtype detection + normalization ----------------
__global__ void k_detect(const long long* __restrict__ edge64, int E) {
    if (threadIdx.x == 0) g_is32 = 0;
    __syncthreads();
    int nscan = E < 4096 ? E : 4096;
    for (int i = threadIdx.x; i < nscan; i += blockDim.x) {
        long long v = edge64[i];
        if (v < 0 || v >= NN) g_is32 = 1;  // benign race
    }
}

__global__ void k_convert(const void* __restrict__ edge, int E) {
    int e = blockIdx.x * blockDim.x + threadIdx.x;
    if (e >= E) return;
    if (g_is32) {
        const int* p = (const int*)edge;
        g_src[e] = p[e];
        g_dst[e] = p[E + e];
    } else {
        const long long* p = (const long long*)edge;
        g_src[e] = (int)p[e];
        g_dst[e] = (int)p[E + e];
    }
}

// ---------------- degree count ----------------
__global__ void k_zero_deg() {
    int i = blockIdx.x * blockDim.x + threadIdx.x;
    if (i < NN) g_degi[i] = 0;
}

__global__ void k_count_deg(int E) {
    int e = blockIdx.x * blockDim.x + threadIdx.x;
    if (e < E) atomicAdd(&g_degi[g_dst[e]], 1);
}

__global__ void k_dinv() {
    int i = blockIdx.x * blockDim.x + threadIdx.x;
    if (i < NN) g_dinv[i] = rsqrtf((float)g_degi[i] + 1.0f);  // +1 self loop
}

// ---------------- prefix scan (3 kernels) ----------------
__global__ void k_scan_part() {
    __shared__ int s[SCH];
    int t = threadIdx.x;
    int i = blockIdx.x * SCH + t;
    s[t] = (i < NN) ? g_degi[i] : 0;
    __syncthreads();
    for (int o = SCH / 2; o > 0; o >>= 1) {
        if (t < o) s[t] += s[t + o];
        __syncthreads();
    }
    if (t == 0) g_part[blockIdx.x] = s[0];
}

__global__ void k_scan_top(int E) {
    __shared__ int s[256];
    int t = threadIdx.x;
    int v = (t < NBLK) ? g_part[t] : 0;
    s[t] = v;
    __syncthreads();
    for (int o = 1; o < 256; o <<= 1) {
        int u = (t >= o) ? s[t - o] : 0;
        __syncthreads();
        s[t] += u;
        __syncthreads();
    }
    if (t < NBLK) g_carry[t] = s[t] - v;  // exclusive
    if (t == 0) g_off[NN] = E;
}

__global__ void k_scan_fin() {
    __shared__ int s[SCH];
    int t = threadIdx.x;
    int i = blockIdx.x * SCH + t;
    int v = (i < NN) ? g_degi[i] : 0;
    s[t] = v;
    __syncthreads();
    for (int o = 1; o < SCH; o <<= 1) {
        int u = (t >= o) ? s[t - o] : 0;
        __syncthreads();
        s[t] += u;
        __syncthreads();
    }
    if (i < NN) {
        int off = g_carry[blockIdx.x] + s[t] - v;  // exclusive
        g_off[i] = off;
        g_cur[i] = off;
    }
}

__global__ void k_fill(int E) {
    int e = blockIdx.x * blockDim.x + threadIdx.x;
    if (e >= E) return;
    int pos = atomicAdd(&g_cur[g_dst[e]], 1);
    g_csr[pos] = g_src[e];
}

__global__ void k_padb2(const float* __restrict__ b2) {
    int i = threadIdx.x;
    if (i < 52) g_b2p[i] = (i < 50) ? b2[i] : 0.0f;
}

// ---------------- gather aggregation ----------------
// out[i] = x[i]*dinv_i^2 + sum_{s in N(i)} x[s]*dinv_s*dinv_i ; optional relu(+bias)
template <int C, int LD, bool BR>
__global__ void k_agg(const float* __restrict__ x, float* __restrict__ out,
                      const float* __restrict__ bias) {
    int idx = blockIdx.x * blockDim.x + threadIdx.x;
    if (idx >= NN * C) return;
    int i = idx / C;
    int c = idx - i * C;
    float di = g_dinv[i];
    float s2 = di * di;
    float4 acc = *(const float4*)(x + (size_t)i * LD + c * 4);
    acc.x *= s2; acc.y *= s2; acc.z *= s2; acc.w *= s2;
    int b = g_off[i], e = g_off[i + 1];
    for (int t = b; t < e; t++) {
        int s = g_csr[t];
        float w = g_dinv[s] * di;
        float4 v = *(const float4*)(x + (size_t)s * LD + c * 4);
        acc.x = fmaf(v.x, w, acc.x);
        acc.y = fmaf(v.y, w, acc.y);
        acc.z = fmaf(v.z, w, acc.z);
        acc.w = fmaf(v.w, w, acc.w);
    }
    if (BR) {
        float4 bb = *(const float4*)(bias + c * 4);
        acc.x = fmaxf(acc.x + bb.x, 0.0f);
        acc.y = fmaxf(acc.y + bb.y, 0.0f);
        acc.z = fmaxf(acc.z + bb.z, 0.0f);
        acc.w = fmaxf(acc.w + bb.w, 0.0f);
    }
    *(float4*)(out + (size_t)i * LD + c * 4) = acc;
}

// ---------------- register-tiled GEMM: Y = X @ W (+bias,relu) ----------------
// X: [n, LDX] (IN valid), W: [IN, OUT] row-major, Y: [n, LDY], OUTP = padded OUT (mult 4, = LDY)
// Block: 64 rows. Threads: 16 rowgroups x (OUTP/4) colgroups. Thread tile 4x4.
template <int IN, int LDX, int OUT, int OUTP, bool BR>
__global__ void k_gemm(const float* __restrict__ X, const float* __restrict__ W,
                       const float* __restrict__ bias, float* __restrict__ Y, int n) {
    constexpr int XS = IN + 1;       // padded stride (bank-conflict free)
    constexpr int CG = OUTP / 4;
    __shared__ float Xs[64 * XS];
    __shared__ float Ws[IN * OUTP];
    int base = blockIdx.x * 64;
    int rows = n - base; if (rows > 64) rows = 64;
    for (int i = threadIdx.x; i < IN * OUTP; i += blockDim.x) {
        int r = i / OUTP, c = i - r * OUTP;
        Ws[i] = (c < OUT) ? W[r * OUT + c] : 0.0f;
    }
    for (int i = threadIdx.x; i < 64 * IN; i += blockDim.x) {
        int r = i / IN, c = i - r * IN;
        Xs[r * XS + c] = (r < rows) ? X[((size_t)base + r) * LDX + c] : 0.0f;
    }
    __syncthreads();
    int tc = threadIdx.x % CG;
    int tr = threadIdx.x / CG;
    int r0 = tr * 4;
    float4 acc0 = {0,0,0,0}, acc1 = {0,0,0,0}, acc2 = {0,0,0,0}, acc3 = {0,0,0,0};
#pragma unroll 2
    for (int k = 0; k < IN; k++) {
        float4 w = *(const float4*)&Ws[k * OUTP + tc * 4];
        float x0 = Xs[(r0 + 0) * XS + k];
        float x1 = Xs[(r0 + 1) * XS + k];
        float x2 = Xs[(r0 + 2) * XS + k];
        float x3 = Xs[(r0 + 3) * XS + k];
        acc0.x = fmaf(x0, w.x, acc0.x); acc0.y = fmaf(x0, w.y, acc0.y);
        acc0.z = fmaf(x0, w.z, acc0.z); acc0.w = fmaf(x0, w.w, acc0.w);
        acc1.x = fmaf(x1, w.x, acc1.x); acc1.y = fmaf(x1, w.y, acc1.y);
        acc1.z = fmaf(x1, w.z, acc1.z); acc1.w = fmaf(x1, w.w, acc1.w);
        acc2.x = fmaf(x2, w.x, acc2.x); acc2.y = fmaf(x2, w.y, acc2.y);
        acc2.z = fmaf(x2, w.z, acc2.z); acc2.w = fmaf(x2, w.w, acc2.w);
        acc3.x = fmaf(x3, w.x, acc3.x); acc3.y = fmaf(x3, w.y, acc3.y);
        acc3.z = fmaf(x3, w.z, acc3.z); acc3.w = fmaf(x3, w.w, acc3.w);
    }
    float4 accs[4] = {acc0, acc1, acc2, acc3};
    float4 bb = {0,0,0,0};
    if (BR) bb = *(const float4*)(bias + tc * 4);
#pragma unroll
    for (int j = 0; j < 4; j++) {
        int r = r0 + j;
        if (r < rows) {
            float4 o = accs[j];
            if (BR) {
                o.x = fmaxf(o.x + bb.x, 0.0f); o.y = fmaxf(o.y + bb.y, 0.0f);
                o.z = fmaxf(o.z + bb.z, 0.0f); o.w = fmaxf(o.w + bb.w, 0.0f);
            }
            *(float4*)(Y + ((size_t)base + r) * OUTP + tc * 4) = o;
        }
    }
}

// ---------------- fused epilogue: relu(agg3+b3) -> MLP 25->25->10->1 ----------------
__global__ void k_final(const float* __restrict__ agg, const float* __restrict__ b3,
                        const float* __restrict__ Wl1, const float* __restrict__ bl1,
                        const float* __restrict__ Wl2, const float* __restrict__ bl2,
                        const float* __restrict__ Wl3, const float* __restrict__ bl3,
                        float* __restrict__ out, int n) {
    __shared__ float sW1[25 * 25], sW2[25 * 10], sW3[10];
    __shared__ float sb3[25], sb1[25], sb2[10], sb3l;
    for (int i = threadIdx.x; i < 25 * 25; i += blockDim.x) sW1[i] = Wl1[i];
    for (int i = threadIdx.x; i < 25 * 10; i += blockDim.x) sW2[i] = Wl2[i];
    if (threadIdx.x < 10) sW3[threadIdx.x] = Wl3[threadIdx.x];
    if (threadIdx.x < 25) { sb3[threadIdx.x] = b3[threadIdx.x]; sb1[threadIdx.x] = bl1[threadIdx.x]; }
    if (threadIdx.x < 10) sb2[threadIdx.x] = bl2[threadIdx.x];
    if (threadIdx.x == 0) sb3l = bl3[0];
    __syncthreads();

    int i = blockIdx.x * blockDim.x + threadIdx.x;
    if (i >= n) return;

    float v[25];
#pragma unroll
    for (int f = 0; f < 25; f++)
        v[f] = fmaxf(agg[(size_t)i * 28 + f] + sb3[f], 0.0f);

    float h1[25];
#pragma unroll
    for (int c = 0; c < 25; c++) {
        float a = sb1[c];
#pragma unroll
        for (int k = 0; k < 25; k++) a = fmaf(v[k], sW1[k * 25 + c], a);
        h1[c] = fmaxf(a, 0.0f);
    }
    float h2[10];
#pragma unroll
    for (int c = 0; c < 10; c++) {
        float a = sb2[c];
#pragma unroll
        for (int k = 0; k < 25; k++) a = fmaf(h1[k], sW2[k * 10 + c], a);
        h2[c] = fmaxf(a, 0.0f);
    }
    float o = sb3l;
#pragma unroll
    for (int k = 0; k < 10; k++) o = fmaf(h2[k], sW3[k], o);
    out[i] = fmaxf(o, 0.0f);
}

// ---------------- launch ----------------
extern "C" void kernel_launch(void* const* d_in, const int* in_sizes, int n_in,
                              void* d_out, int out_size) {
    const float* x   = (const float*)d_in[0];
    const float* W1  = (const float*)d_in[1];
    const float* b1  = (const float*)d_in[2];
    const float* W2  = (const float*)d_in[3];
    const float* b2  = (const float*)d_in[4];
    const float* W3  = (const float*)d_in[5];
    const float* b3  = (const float*)d_in[6];
    const float* Wl1 = (const float*)d_in[7];
    const float* bl1 = (const float*)d_in[8];
    const float* Wl2 = (const float*)d_in[9];
    const float* bl2 = (const float*)d_in[10];
    const float* Wl3 = (const float*)d_in[11];
    const float* bl3 = (const float*)d_in[12];
    const void* edge = d_in[13];
    int E = in_sizes[13] / 2;

    float *A, *B, *C, *b2p;
    cudaGetSymbolAddress((void**)&A, g_bufA);
    cudaGetSymbolAddress((void**)&B, g_bufB);
    cudaGetSymbolAddress((void**)&C, g_bufC);
    cudaGetSymbolAddress((void**)&b2p, g_b2p);

    const int T = 256;
    int gN = (NN + T - 1) / T;
    int gE = (E + T - 1) / T;

    // edge normalization + CSR build (once per launch, shared by 3 layers)
    k_detect<<<1, 256>>>((const long long*)edge, E);
    k_convert<<<gE, T>>>(edge, E);
    k_zero_deg<<<gN, T>>>();
    k_count_deg<<<gE, T>>>(E);
    k_dinv<<<gN, T>>>();
    k_scan_part<<<NBLK, SCH>>>();
    k_scan_top<<<1, 256>>>(E);
    k_scan_fin<<<NBLK, SCH>>>();
    k_fill<<<gE, T>>>(E);
    k_padb2<<<1, 64>>>(b2);

    int gemmG = (NN + 63) / 64;

    // ----- Layer 1: aggregate input (64-dim), GEMM 64->100 (+b1, relu) -----
    k_agg<16, 64, false><<<(NN * 16 + T - 1) / T, T>>>(x, A, nullptr);
    k_gemm<64, 64, 100, 100, true><<<gemmG, 16 * (100 / 4)>>>(A, W1, b1, B, NN);

    // ----- Layer 2: GEMM 100->50 raw (pad 52), aggregate w/ fused relu(+b2) -----
    k_gemm<100, 100, 50, 52, false><<<gemmG, 16 * (52 / 4)>>>(B, W2, nullptr, A, NN);
    k_agg<13, 52, true><<<(NN * 13 + T - 1) / T, T>>>(A, C, b2p);

    // ----- Layer 3: GEMM 50->25 raw (pad 28), aggregate raw -----
    k_gemm<50, 52, 25, 28, false><<<gemmG, 16 * (28 / 4)>>>(C, W3, nullptr, A, NN);
    k_agg<7, 28, false><<<(NN * 7 + T - 1) / T, T>>>(A, B, nullptr);

    // ----- fused: relu(agg3+b3) -> MLP 25->25->10->1 -----
    k_final<<<gN, T>>>(B, b3, Wl1, bl1, Wl2, bl2, Wl3, bl3, (float*)d_out, NN);
}